// round 2
// baseline (speedup 1.0000x reference)
#include <cuda_runtime.h>
#include <math.h>

#define Hh 256
#define N2d 32
#define Bb 8
#define Ll 4096

// -------- scratch (no allocations allowed) --------
__device__ float g_lam_re[Hh*N2d], g_lam_im[Hh*N2d];
__device__ float g_c_re[Hh*N2d],   g_c_im[Hh*N2d];
__device__ float g_Y[(size_t)Bb*Hh*Ll];   // post-GELU activations, 33.5 MB

// ============================================================
// Kernel 1: per-(h,n) discretization:
//   lambda = exp(dt*A),  c = 2*C*(exp(dt*A)-1)/A
// ============================================================
__global__ void prep_kernel(const float* __restrict__ log_dt,
                            const float* __restrict__ C,
                            const float* __restrict__ log_A_real,
                            const float* __restrict__ A_imag) {
    int idx = blockIdx.x*blockDim.x + threadIdx.x;
    if (idx >= Hh*N2d) return;
    int h = idx / N2d;
    float dt  = expf(log_dt[h]);
    float Are = -expf(log_A_real[idx]);
    float Aim = A_imag[idx];
    float dr = Are*dt, di = Aim*dt;
    float er = expf(dr);
    float lr = er*cosf(di), li = er*sinf(di);
    // (lambda - 1) / A
    float e1r = lr - 1.0f, e1i = li;
    float den = Are*Are + Aim*Aim;
    float ir =  Are/den, ii = -Aim/den;
    float tr = e1r*ir - e1i*ii;
    float ti = e1r*ii + e1i*ir;
    float Cr = C[2*idx], Ci = C[2*idx+1];
    float cr = Cr*tr - Ci*ti;
    float ci = Cr*ti + Ci*tr;
    g_lam_re[idx] = lr;  g_lam_im[idx] = li;
    g_c_re[idx] = 2.0f*cr;  g_c_im[idx] = 2.0f*ci;
}

// ============================================================
// Kernel 2: diagonal-SSM scan. One warp per (b,h), lane = mode n.
//   t = lambda*t + c*u[l] ;  y_raw[l] = sum_n Re(t_n)
// Contributions staged in smem tile[step][mode]; each lane then sums
// over modes for its step, fuses skip (D*u) + exact GELU, writes g_Y.
// ============================================================
__global__ void __launch_bounds__(256) scan_kernel(const float* __restrict__ u,
                                                   const float* __restrict__ D) {
    __shared__ float tile[8][32][33];
    int w    = threadIdx.x >> 5;
    int lane = threadIdx.x & 31;
    int wg   = blockIdx.x*8 + w;          // 0..2047
    int b    = wg >> 8;
    int h    = wg & 255;
    const float* up = u   + (size_t)(b*Hh + h)*Ll;
    float*       yp = g_Y + (size_t)(b*Hh + h)*Ll;
    int ci = h*N2d + lane;
    float lr = g_lam_re[ci], li = g_lam_im[ci];
    float cr = g_c_re[ci],   cim = g_c_im[ci];
    float Dh = D[h];
    float tre = 0.0f, tim = 0.0f;

    for (int ch = 0; ch < Ll/32; ++ch) {
        float uv = up[ch*32 + lane];
        #pragma unroll
        for (int i = 0; i < 32; ++i) {
            float ul = __shfl_sync(0xffffffffu, uv, i);
            float pr = tre, pi = tim;
            tre = fmaf(lr, pr, fmaf(-li, pi, cr*ul));
            tim = fmaf(lr, pi, fmaf( li, pr, cim*ul));
            tile[w][i][lane] = tre;   // [step i][mode lane]
        }
        __syncwarp();
        // lane = output step: sum over modes j
        float acc = 0.0f;
        #pragma unroll
        for (int j = 0; j < 32; ++j) acc += tile[w][lane][j];
        float y = fmaf(Dh, uv, acc);
        float g = 0.5f*y*(1.0f + erff(y*0.70710678118654752f));  // exact GELU
        yp[ch*32 + lane] = g;
        __syncwarp();
    }
}

// ============================================================
// Kernel 3: fused 1x1 conv (H->2H) + GLU, fp32 via packed f32x2 FMA.
// Block tile: 64 h-rows (both 'a' and 'g' halves) x 128 l-cols, K=256.
// ============================================================
__device__ __forceinline__ unsigned long long pk2(float a, float b) {
    unsigned long long r;
    asm("mov.b64 %0, {%1,%2};" : "=l"(r) : "f"(a), "f"(b));
    return r;
}
__device__ __forceinline__ void upk2(unsigned long long v, float& a, float& b) {
    asm("mov.b64 {%0,%1}, %2;" : "=f"(a), "=f"(b) : "l"(v));
}
__device__ __forceinline__ void fma2(unsigned long long& d,
                                     unsigned long long a, unsigned long long b) {
    asm("fma.rn.f32x2 %0, %1, %2, %0;" : "+l"(d) : "l"(a), "l"(b));
}

__global__ void __launch_bounds__(256) gemm_glu_kernel(const float* __restrict__ Wm,
                                                       const float* __restrict__ bias,
                                                       float* __restrict__ out) {
    __shared__ float sWa[16][68];   // transposed W rows [h0,h0+64), pad avoids conflicts
    __shared__ float sWg[16][68];   // transposed W rows [256+h0, 256+h0+64)
    __shared__ float sY [16][128];

    int tid = threadIdx.x;
    int l0 = blockIdx.x*128, h0 = blockIdx.y*64, b = blockIdx.z;
    int tx = tid & 15;   // l-subtile: 8 columns at l0+tx*8
    int ty = tid >> 4;   // h-subtile: 4 rows at h0+ty*4
    const float* Yb = g_Y + (size_t)b*Hh*Ll;

    unsigned long long aa[4][4], ag[4][4];
    #pragma unroll
    for (int j = 0; j < 4; ++j)
        #pragma unroll
        for (int p = 0; p < 4; ++p) { aa[j][p] = 0ULL; ag[j][p] = 0ULL; }

    int m  = tid >> 2;   // 0..63  (W row within tile)
    int kq = tid & 3;    // 0..3   (which float4 of the 16 k's)

    for (int ks = 0; ks < 16; ++ks) {
        int k0 = ks*16;
        __syncthreads();
        // Y tile: 16 k-rows x 128 l, 512 float4 loads
        #pragma unroll
        for (int p = 0; p < 2; ++p) {
            int idx4 = tid + p*256;
            int row = idx4 >> 5, c4 = idx4 & 31;
            float4 v = *(const float4*)(Yb + (size_t)(k0+row)*Ll + l0 + c4*4);
            *(float4*)&sY[row][c4*4] = v;
        }
        // W tiles (coalesced along k, scatter-transposed into smem)
        float4 wa = *(const float4*)(Wm + (size_t)(h0+m)*Hh      + k0 + kq*4);
        float4 wg = *(const float4*)(Wm + (size_t)(Hh+h0+m)*Hh   + k0 + kq*4);
        sWa[kq*4+0][m]=wa.x; sWa[kq*4+1][m]=wa.y; sWa[kq*4+2][m]=wa.z; sWa[kq*4+3][m]=wa.w;
        sWg[kq*4+0][m]=wg.x; sWg[kq*4+1][m]=wg.y; sWg[kq*4+2][m]=wg.z; sWg[kq*4+3][m]=wg.w;
        __syncthreads();

        #pragma unroll
        for (int kk = 0; kk < 16; ++kk) {
            ulonglong2 y01 = *(const ulonglong2*)&sY[kk][tx*8];
            ulonglong2 y23 = *(const ulonglong2*)&sY[kk][tx*8 + 4];
            unsigned long long yp4[4] = { y01.x, y01.y, y23.x, y23.y };
            float4 wa4 = *(const float4*)&sWa[kk][ty*4];
            float4 wg4 = *(const float4*)&sWg[kk][ty*4];
            unsigned long long wpa[4] = { pk2(wa4.x,wa4.x), pk2(wa4.y,wa4.y),
                                          pk2(wa4.z,wa4.z), pk2(wa4.w,wa4.w) };
            unsigned long long wpg[4] = { pk2(wg4.x,wg4.x), pk2(wg4.y,wg4.y),
                                          pk2(wg4.z,wg4.z), pk2(wg4.w,wg4.w) };
            #pragma unroll
            for (int j = 0; j < 4; ++j)
                #pragma unroll
                for (int p = 0; p < 4; ++p) {
                    fma2(aa[j][p], wpa[j], yp4[p]);
                    fma2(ag[j][p], wpg[j], yp4[p]);
                }
        }
    }

    // epilogue: bias + GLU (a * sigmoid(g))
    #pragma unroll
    for (int j = 0; j < 4; ++j) {
        int h = h0 + ty*4 + j;
        float bh = bias[h], bg = bias[Hh + h];
        float ov[8];
        #pragma unroll
        for (int p = 0; p < 4; ++p) {
            float a0,a1,g0,g1;
            upk2(aa[j][p], a0, a1);
            upk2(ag[j][p], g0, g1);
            a0 += bh; a1 += bh; g0 += bg; g1 += bg;
            ov[2*p]   = a0 / (1.0f + expf(-g0));
            ov[2*p+1] = a1 / (1.0f + expf(-g1));
        }
        float* op = out + ((size_t)(b*Hh) + h)*Ll + l0 + tx*8;
        *(float4*)op     = make_float4(ov[0],ov[1],ov[2],ov[3]);
        *(float4*)(op+4) = make_float4(ov[4],ov[5],ov[6],ov[7]);
    }
}

// ============================================================
extern "C" void kernel_launch(void* const* d_in, const int* in_sizes, int n_in,
                              void* d_out, int out_size) {
    const float* u       = (const float*)d_in[0];
    const float* log_dt  = (const float*)d_in[1];
    const float* C       = (const float*)d_in[2];
    const float* lar     = (const float*)d_in[3];
    const float* aim     = (const float*)d_in[4];
    const float* D       = (const float*)d_in[5];
    const float* Wm      = (const float*)d_in[6];
    const float* bias    = (const float*)d_in[7];
    float* out = (float*)d_out;

    prep_kernel<<<(Hh*N2d + 255)/256, 256>>>(log_dt, C, lar, aim);
    scan_kernel<<<(Bb*Hh)/8, 256>>>(u, D);
    dim3 grid(Ll/128, Hh/64, Bb);
    gemm_glu_kernel<<<grid, 256>>>(Wm, bias, out);
}

// round 5
// speedup vs baseline: 1.2338x; 1.2338x over previous
#include <cuda_runtime.h>
#include <cuda_bf16.h>
#include <math.h>
#include <stdint.h>

#define Hh 256
#define N2d 32
#define Bb 8
#define Ll 4096

// -------- scratch (no allocations allowed) --------
__device__ float g_lam_re[Hh*N2d], g_lam_im[Hh*N2d];
__device__ float g_c_re[Hh*N2d],   g_c_im[Hh*N2d];
__device__ __align__(16) __nv_bfloat16 g_Whi[2*Hh*Hh], g_Wlo[2*Hh*Hh];
// Y transposed: [b][l][h], h contiguous. hi/lo bf16 split of post-GELU activations.
__device__ __align__(16) __nv_bfloat16 g_Yhi[(size_t)Bb*Ll*Hh];
__device__ __align__(16) __nv_bfloat16 g_Ylo[(size_t)Bb*Ll*Hh];

__device__ __forceinline__ uint32_t smem_u32(const void* p) {
    uint32_t a;
    asm("{ .reg .u64 t; cvta.to.shared.u64 t, %1; cvt.u32.u64 %0, t; }" : "=r"(a) : "l"(p));
    return a;
}
__device__ __forceinline__ void ldsm4(uint32_t* r, uint32_t a) {
    asm volatile("ldmatrix.sync.aligned.m8n8.x4.shared.b16 {%0,%1,%2,%3}, [%4];"
                 : "=r"(r[0]), "=r"(r[1]), "=r"(r[2]), "=r"(r[3]) : "r"(a));
}
__device__ __forceinline__ void mma16816(float* c, const uint32_t* a,
                                         uint32_t b0, uint32_t b1) {
    asm volatile(
        "mma.sync.aligned.m16n8k16.row.col.f32.bf16.bf16.f32 "
        "{%0,%1,%2,%3}, {%4,%5,%6,%7}, {%8,%9}, {%0,%1,%2,%3};"
        : "+f"(c[0]), "+f"(c[1]), "+f"(c[2]), "+f"(c[3])
        : "r"(a[0]), "r"(a[1]), "r"(a[2]), "r"(a[3]), "r"(b0), "r"(b1));
}

// ============================================================
// Kernel 1a: discretization  lambda = exp(dt*A),  c = 2*C*(lambda-1)/A
// ============================================================
__global__ void prep_kernel(const float* __restrict__ log_dt,
                            const float* __restrict__ C,
                            const float* __restrict__ log_A_real,
                            const float* __restrict__ A_imag) {
    int idx = blockIdx.x*blockDim.x + threadIdx.x;
    if (idx >= Hh*N2d) return;
    int h = idx / N2d;
    float dt  = expf(log_dt[h]);
    float Are = -expf(log_A_real[idx]);
    float Aim = A_imag[idx];
    float dr = Are*dt, di = Aim*dt;
    float er = expf(dr);
    float lr = er*cosf(di), li = er*sinf(di);
    float e1r = lr - 1.0f, e1i = li;
    float den = Are*Are + Aim*Aim;
    float ir =  Are/den, ii = -Aim/den;
    float tr = e1r*ir - e1i*ii;
    float ti = e1r*ii + e1i*ir;
    float Cr = C[2*idx], Ci = C[2*idx+1];
    g_lam_re[idx] = lr;  g_lam_im[idx] = li;
    g_c_re[idx] = 2.0f*(Cr*tr - Ci*ti);
    g_c_im[idx] = 2.0f*(Cr*ti + Ci*tr);
}

// ============================================================
// Kernel 1b: W -> bf16 hi/lo split
// ============================================================
__global__ void wsplit_kernel(const float* __restrict__ W) {
    int i = blockIdx.x*blockDim.x + threadIdx.x;
    if (i >= 2*Hh*Hh) return;
    float v = W[i];
    __nv_bfloat16 hi = __float2bfloat16(v);
    g_Whi[i] = hi;
    g_Wlo[i] = __float2bfloat16(v - __bfloat162float(hi));
}

// ============================================================
// Kernel 2: diagonal-SSM scan. One warp per (b,h), lane = mode n.
// Per 32-step chunk: recurrence + mode reduction + skip + exact GELU,
// then bf16 hi/lo split + block transpose -> Yt[b][l][h] (h contig).
// ============================================================
__global__ void __launch_bounds__(256) scan_kernel(const float* __restrict__ u,
                                                   const float* __restrict__ D) {
    __shared__ float tile[8][32][33];
    __shared__ uint32_t sh[32][9];   // packed (hi | lo<<16) per [l-row][warp]
    int w    = threadIdx.x >> 5;
    int lane = threadIdx.x & 31;
    int wg   = blockIdx.x*8 + w;          // 0..2047
    int b    = wg >> 8;
    int h    = wg & 255;
    int h0b  = (blockIdx.x*8) & 255;      // first h of this block (8-aligned)
    const float* up = u + (size_t)(b*Hh + h)*Ll;
    int ci = h*N2d + lane;
    float lr = g_lam_re[ci], li = g_lam_im[ci];
    float cr = g_c_re[ci],   cim = g_c_im[ci];
    float Dh = D[h];
    float tre = 0.0f, tim = 0.0f;

    for (int ch = 0; ch < Ll/32; ++ch) {
        float uv = up[ch*32 + lane];
        #pragma unroll
        for (int i = 0; i < 32; ++i) {
            float ul = __shfl_sync(0xffffffffu, uv, i);
            float pr = tre, pi = tim;
            tre = fmaf(lr, pr, fmaf(-li, pi, cr*ul));
            tim = fmaf(lr, pi, fmaf( li, pr, cim*ul));
            tile[w][i][lane] = tre;   // [step i][mode lane]
        }
        __syncwarp();
        float acc = 0.0f;
        #pragma unroll
        for (int j = 0; j < 32; ++j) acc += tile[w][lane][j];
        float y = fmaf(Dh, uv, acc);
        float g = 0.5f*y*(1.0f + erff(y*0.70710678118654752f));  // exact GELU
        __nv_bfloat16 hi = __float2bfloat16(g);
        __nv_bfloat16 lo = __float2bfloat16(g - __bfloat162float(hi));
        sh[lane][w] = (uint32_t)__bfloat16_as_ushort(hi)
                    | ((uint32_t)__bfloat16_as_ushort(lo) << 16);
        __syncthreads();
        if (threadIdx.x < 64) {
            int arr = threadIdx.x >> 5;   // 0 = hi, 1 = lo
            int r   = threadIdx.x & 31;   // l-row
            uint32_t vrow[8];
            #pragma unroll
            for (int j = 0; j < 8; ++j) {
                uint32_t v = sh[r][j];
                vrow[j] = arr ? (v >> 16) : (v & 0xffffu);
            }
            uint4 o;
            o.x = vrow[0] | (vrow[1] << 16);
            o.y = vrow[2] | (vrow[3] << 16);
            o.z = vrow[4] | (vrow[5] << 16);
            o.w = vrow[6] | (vrow[7] << 16);
            __nv_bfloat16* base = arr ? g_Ylo : g_Yhi;
            *(uint4*)(base + ((size_t)b*Ll + ch*32 + r)*Hh + h0b) = o;
        }
        __syncthreads();
    }
}

// ============================================================
// Kernel 3: mma.sync (HMMA.16816 bf16) split GEMM + bias + GLU.
// CTA: 128 h-rows ('a' AND paired 'g' rows) x 128 l-cols, K=256.
// 8 warps = 2(M) x 4(N); warp tile 64x32 per half. Double-buffered
// smem, k-step 16, ldmatrix with 48B-padded rows (conflict-free).
// B (Y) stored [n=l][k=h] -> NON-trans ldmatrix gives the col-major
// B fragment directly. GLU fused in-register.
// ============================================================
#define ROWB 48                      // padded smem row stride in bytes (16 bf16 used)
#define BUFB (128*ROWB)              // one 128-row operand buffer = 6144B
#define STAGE (6*BUFB)               // Aah,Aal,Agh,Agl,Bh,Bl = 36864B
#define GEMM_SMEM (2*STAGE)

__global__ void __launch_bounds__(256, 1) gemm_mma_kernel(const float* __restrict__ bias,
                                                          float* __restrict__ out) {
    extern __shared__ char smem[];
    const uint32_t sb = smem_u32(smem);

    const int tid  = threadIdx.x;
    const int lane = tid & 31;
    const int w    = tid >> 5;
    const int wm   = w >> 2;          // 0..1  (64-row group)
    const int wn   = w & 3;           // 0..3  (32-col group)
    const int l0 = blockIdx.x*128;
    const int h0 = blockIdx.y*128;
    const int b  = blockIdx.z;

    // gmem staging pointers (row = tid>>1, seg = tid&1 -> 16B each)
    const int row = tid >> 1, seg = tid & 1;
    const __nv_bfloat16* pAah = g_Whi + (size_t)(h0+row)*Hh      + seg*8;
    const __nv_bfloat16* pAal = g_Wlo + (size_t)(h0+row)*Hh      + seg*8;
    const __nv_bfloat16* pAgh = g_Whi + (size_t)(Hh+h0+row)*Hh   + seg*8;
    const __nv_bfloat16* pAgl = g_Wlo + (size_t)(Hh+h0+row)*Hh   + seg*8;
    const __nv_bfloat16* pBh  = g_Yhi + ((size_t)b*Ll + l0+row)*Hh + seg*8;
    const __nv_bfloat16* pBl  = g_Ylo + ((size_t)b*Ll + l0+row)*Hh + seg*8;
    const uint32_t sts = (uint32_t)(row*ROWB + seg*16);

    // ldmatrix lane addressing (within a buffer)
    const uint32_t a_off = (uint32_t)((lane & 15)*ROWB + (lane >> 4)*16);
    // B (non-trans): lanes 0-7: rows n0-7 @k0-7; 8-15: n0-7 @k8-15;
    //                16-23: n8-15 @k0-7; 24-31: n8-15 @k8-15
    const uint32_t b_off = (uint32_t)((((lane & 7) + ((lane >> 4) & 1)*8))*ROWB
                                      + ((lane >> 3) & 1)*16);

    float acc_a[4][4][4], acc_g[4][4][4];
    #pragma unroll
    for (int i = 0; i < 4; ++i)
        #pragma unroll
        for (int j = 0; j < 4; ++j)
            #pragma unroll
            for (int q = 0; q < 4; ++q) { acc_a[i][j][q] = 0.f; acc_g[i][j][q] = 0.f; }

    // ---- prologue: load k-step 0 ----
    uint4 st[6];
    st[0] = *(const uint4*)pAah; st[1] = *(const uint4*)pAal;
    st[2] = *(const uint4*)pAgh; st[3] = *(const uint4*)pAgl;
    st[4] = *(const uint4*)pBh;  st[5] = *(const uint4*)pBl;
    #pragma unroll
    for (int t = 0; t < 6; ++t)
        *(uint4*)(smem + t*BUFB + sts) = st[t];
    __syncthreads();

    #pragma unroll
    for (int ks = 0; ks < 16; ++ks) {
        const uint32_t cur = (uint32_t)((ks & 1)*STAGE);
        if (ks < 15) {
            int k0 = (ks+1)*16;
            st[0] = *(const uint4*)(pAah + k0); st[1] = *(const uint4*)(pAal + k0);
            st[2] = *(const uint4*)(pAgh + k0); st[3] = *(const uint4*)(pAgl + k0);
            st[4] = *(const uint4*)(pBh  + k0); st[5] = *(const uint4*)(pBl  + k0);
        }
        // ---- B fragments: 4 n8-blocks, hi and lo (NON-trans ldmatrix) ----
        uint32_t bh[8], bl[8];
        {
            uint32_t base_h = sb + cur + 4*BUFB + b_off;
            uint32_t base_l = sb + cur + 5*BUFB + b_off;
            ldsm4(&bh[0], base_h + (uint32_t)(wn*32)*ROWB);
            ldsm4(&bh[4], base_h + (uint32_t)(wn*32+16)*ROWB);
            ldsm4(&bl[0], base_l + (uint32_t)(wn*32)*ROWB);
            ldsm4(&bl[4], base_l + (uint32_t)(wn*32+16)*ROWB);
        }
        #pragma unroll
        for (int i = 0; i < 4; ++i) {
            uint32_t moff = (uint32_t)(wm*64 + i*16)*ROWB + a_off;
            uint32_t ah[4], al[4];
            ldsm4(ah, sb + cur + 0*BUFB + moff);
            ldsm4(al, sb + cur + 1*BUFB + moff);
            #pragma unroll
            for (int j = 0; j < 4; ++j) {
                mma16816(acc_a[i][j], ah, bh[2*j], bh[2*j+1]);
                mma16816(acc_a[i][j], ah, bl[2*j], bl[2*j+1]);
                mma16816(acc_a[i][j], al, bh[2*j], bh[2*j+1]);
            }
            ldsm4(ah, sb + cur + 2*BUFB + moff);
            ldsm4(al, sb + cur + 3*BUFB + moff);
            #pragma unroll
            for (int j = 0; j < 4; ++j) {
                mma16816(acc_g[i][j], ah, bh[2*j], bh[2*j+1]);
                mma16816(acc_g[i][j], ah, bl[2*j], bl[2*j+1]);
                mma16816(acc_g[i][j], al, bh[2*j], bh[2*j+1]);
            }
        }
        if (ks < 15) {
            char* nxt = smem + ((ks+1) & 1)*STAGE;
            #pragma unroll
            for (int t = 0; t < 6; ++t)
                *(uint4*)(nxt + t*BUFB + sts) = st[t];
        }
        __syncthreads();
    }

    // ---- epilogue: bias + GLU, in-register ----
    #pragma unroll
    for (int i = 0; i < 4; ++i) {
        int hr = h0 + wm*64 + i*16 + (lane >> 2);
        float ba0 = bias[hr],     bg0 = bias[Hh + hr];
        float ba1 = bias[hr + 8], bg1 = bias[Hh + hr + 8];
        #pragma unroll
        for (int j = 0; j < 4; ++j) {
            int col = l0 + wn*32 + j*8 + (lane & 3)*2;
            float a0 = acc_a[i][j][0] + ba0, g0 = acc_g[i][j][0] + bg0;
            float a1 = acc_a[i][j][1] + ba0, g1 = acc_g[i][j][1] + bg0;
            float a2 = acc_a[i][j][2] + ba1, g2 = acc_g[i][j][2] + bg1;
            float a3 = acc_a[i][j][3] + ba1, g3 = acc_g[i][j][3] + bg1;
            float2 v0 = make_float2(a0 / (1.0f + expf(-g0)),
                                    a1 / (1.0f + expf(-g1)));
            float2 v1 = make_float2(a2 / (1.0f + expf(-g2)),
                                    a3 / (1.0f + expf(-g3)));
            *(float2*)(out + ((size_t)b*Hh + hr)*Ll + col)     = v0;
            *(float2*)(out + ((size_t)b*Hh + hr + 8)*Ll + col) = v1;
        }
    }
}

// ============================================================
extern "C" void kernel_launch(void* const* d_in, const int* in_sizes, int n_in,
                              void* d_out, int out_size) {
    const float* u       = (const float*)d_in[0];
    const float* log_dt  = (const float*)d_in[1];
    const float* C       = (const float*)d_in[2];
    const float* lar     = (const float*)d_in[3];
    const float* aim     = (const float*)d_in[4];
    const float* D       = (const float*)d_in[5];
    const float* Wm      = (const float*)d_in[6];
    const float* bias    = (const float*)d_in[7];
    float* out = (float*)d_out;

    cudaFuncSetAttribute(gemm_mma_kernel,
                         cudaFuncAttributeMaxDynamicSharedMemorySize, GEMM_SMEM);

    prep_kernel<<<(Hh*N2d + 255)/256, 256>>>(log_dt, C, lar, aim);
    wsplit_kernel<<<(2*Hh*Hh + 255)/256, 256>>>(Wm);
    scan_kernel<<<(Bb*Hh)/8, 256>>>(u, D);
    dim3 grid(Ll/128, Hh/128, Bb);
    gemm_mma_kernel<<<grid, 256, GEMM_SMEM>>>(bias, out);
}

// round 6
// speedup vs baseline: 1.2978x; 1.0519x over previous
#include <cuda_runtime.h>
#include <cuda_bf16.h>
#include <math.h>
#include <stdint.h>

#define Hh 256
#define N2d 32
#define Bb 8
#define Ll 4096

// -------- scratch (no allocations allowed) --------
__device__ float g_lam_re[Hh*N2d], g_lam_im[Hh*N2d];
__device__ float g_c_re[Hh*N2d],   g_c_im[Hh*N2d];
__device__ __align__(16) __nv_bfloat16 g_Whi[2*Hh*Hh], g_Wlo[2*Hh*Hh];
// Y natural layout: [b][h][l], l contiguous. hi/lo bf16 split of post-GELU activations.
__device__ __align__(16) __nv_bfloat16 g_Yhi[(size_t)Bb*Hh*Ll];
__device__ __align__(16) __nv_bfloat16 g_Ylo[(size_t)Bb*Hh*Ll];

__device__ __forceinline__ uint32_t smem_u32(const void* p) {
    uint32_t a;
    asm("{ .reg .u64 t; cvta.to.shared.u64 t, %1; cvt.u32.u64 %0, t; }" : "=r"(a) : "l"(p));
    return a;
}
__device__ __forceinline__ void ldsm4(uint32_t* r, uint32_t a) {
    asm volatile("ldmatrix.sync.aligned.m8n8.x4.shared.b16 {%0,%1,%2,%3}, [%4];"
                 : "=r"(r[0]), "=r"(r[1]), "=r"(r[2]), "=r"(r[3]) : "r"(a));
}
__device__ __forceinline__ void ldsm4t(uint32_t* r, uint32_t a) {
    asm volatile("ldmatrix.sync.aligned.m8n8.x4.trans.shared.b16 {%0,%1,%2,%3}, [%4];"
                 : "=r"(r[0]), "=r"(r[1]), "=r"(r[2]), "=r"(r[3]) : "r"(a));
}
__device__ __forceinline__ void mma16816(float* c, const uint32_t* a,
                                         uint32_t b0, uint32_t b1) {
    asm volatile(
        "mma.sync.aligned.m16n8k16.row.col.f32.bf16.bf16.f32 "
        "{%0,%1,%2,%3}, {%4,%5,%6,%7}, {%8,%9}, {%0,%1,%2,%3};"
        : "+f"(c[0]), "+f"(c[1]), "+f"(c[2]), "+f"(c[3])
        : "r"(a[0]), "r"(a[1]), "r"(a[2]), "r"(a[3]), "r"(b0), "r"(b1));
}
__device__ __forceinline__ void cpa16(uint32_t dst, const void* src) {
    asm volatile("cp.async.cg.shared.global [%0], [%1], 16;" :: "r"(dst), "l"(src));
}

// ============================================================
// Kernel 1a: discretization  lambda = exp(dt*A),  c = 2*C*(lambda-1)/A
// ============================================================
__global__ void prep_kernel(const float* __restrict__ log_dt,
                            const float* __restrict__ C,
                            const float* __restrict__ log_A_real,
                            const float* __restrict__ A_imag) {
    int idx = blockIdx.x*blockDim.x + threadIdx.x;
    if (idx >= Hh*N2d) return;
    int h = idx / N2d;
    float dt  = expf(log_dt[h]);
    float Are = -expf(log_A_real[idx]);
    float Aim = A_imag[idx];
    float dr = Are*dt, di = Aim*dt;
    float er = expf(dr);
    float lr = er*cosf(di), li = er*sinf(di);
    float e1r = lr - 1.0f, e1i = li;
    float den = Are*Are + Aim*Aim;
    float ir =  Are/den, ii = -Aim/den;
    float tr = e1r*ir - e1i*ii;
    float ti = e1r*ii + e1i*ir;
    float Cr = C[2*idx], Ci = C[2*idx+1];
    g_lam_re[idx] = lr;  g_lam_im[idx] = li;
    g_c_re[idx] = 2.0f*(Cr*tr - Ci*ti);
    g_c_im[idx] = 2.0f*(Cr*ti + Ci*tr);
}

// ============================================================
// Kernel 1b: W -> bf16 hi/lo split
// ============================================================
__global__ void wsplit_kernel(const float* __restrict__ W) {
    int i = blockIdx.x*blockDim.x + threadIdx.x;
    if (i >= 2*Hh*Hh) return;
    float v = W[i];
    __nv_bfloat16 hi = __float2bfloat16(v);
    g_Whi[i] = hi;
    g_Wlo[i] = __float2bfloat16(v - __bfloat162float(hi));
}

// ============================================================
// Kernel 2: diagonal-SSM scan. One warp per (b,h), lane = mode n.
// Fully warp-local: no __syncthreads, no block transpose. Output in
// natural [b][h][l] layout as bf16 hi/lo.
// ============================================================
__global__ void __launch_bounds__(256) scan_kernel(const float* __restrict__ u,
                                                   const float* __restrict__ D) {
    __shared__ float tile[8][32][33];
    int w    = threadIdx.x >> 5;
    int lane = threadIdx.x & 31;
    int wg   = blockIdx.x*8 + w;          // 0..2047
    int b    = wg >> 8;
    int h    = wg & 255;
    const float* up = u + (size_t)(b*Hh + h)*Ll;
    __nv_bfloat16* yh = g_Yhi + (size_t)(b*Hh + h)*Ll;
    __nv_bfloat16* yl = g_Ylo + (size_t)(b*Hh + h)*Ll;
    int ci = h*N2d + lane;
    float lr = g_lam_re[ci], li = g_lam_im[ci];
    float cr = g_c_re[ci],   cim = g_c_im[ci];
    float Dh = D[h];
    float tre = 0.0f, tim = 0.0f;

    for (int ch = 0; ch < Ll/32; ++ch) {
        float uv = up[ch*32 + lane];
        #pragma unroll
        for (int i = 0; i < 32; ++i) {
            float ul = __shfl_sync(0xffffffffu, uv, i);
            float pr = tre, pi = tim;
            tre = fmaf(lr, pr, fmaf(-li, pi, cr*ul));
            tim = fmaf(lr, pi, fmaf( li, pr, cim*ul));
            tile[w][i][lane] = tre;   // [step i][mode lane]
        }
        __syncwarp();
        float acc = 0.0f;
        #pragma unroll
        for (int j = 0; j < 32; ++j) acc += tile[w][lane][j];
        float y = fmaf(Dh, uv, acc);
        float g = 0.5f*y*(1.0f + erff(y*0.70710678118654752f));  // exact GELU
        __nv_bfloat16 hi = __float2bfloat16(g);
        __nv_bfloat16 lo = __float2bfloat16(g - __bfloat162float(hi));
        yh[ch*32 + lane] = hi;
        yl[ch*32 + lane] = lo;
        __syncwarp();
    }
}

// ============================================================
// Kernel 3: HMMA.16816 bf16-split GEMM + bias + GLU.
// CTA: 128 h-rows ('a' AND paired 'g' rows) x 128 l-cols, K=256.
// 3-stage cp.async pipeline. A staged [m][k] (48B rows), B staged
// [k][n] (272B rows) and read with ldmatrix.trans -> col-major B frag.
// GLU fused in-register.
// ============================================================
#define AROW 48
#define ABUF (128*AROW)              // 6144B per A array
#define BROW 272
#define BBUF (16*BROW)               // 4352B per B array
#define BOFF (4*ABUF)                // B arrays after 4 A arrays
#define STAGEB (4*ABUF + 2*BBUF)     // 33280B
#define GEMM_SMEM (3*STAGEB)         // 99840B

__global__ void __launch_bounds__(256, 1) gemm_mma_kernel(const float* __restrict__ bias,
                                                          float* __restrict__ out) {
    extern __shared__ char smem[];
    const uint32_t sb = smem_u32(smem);

    const int tid  = threadIdx.x;
    const int lane = tid & 31;
    const int w    = tid >> 5;
    const int wm   = w >> 2;          // 0..1  (64-row group)
    const int wn   = w & 3;           // 0..3  (32-col group)
    const int l0 = blockIdx.x*128;
    const int h0 = blockIdx.y*128;
    const int b  = blockIdx.z;

    // ---- cp.async source pointers ----
    // A: row = tid>>1 (0..127), chunk = tid&1 (16B each of 32B row)
    const int arow = tid >> 1, ach = tid & 1;
    const __nv_bfloat16* pA[4];
    pA[0] = g_Whi + (size_t)(h0+arow)*Hh      + ach*8;
    pA[1] = g_Wlo + (size_t)(h0+arow)*Hh      + ach*8;
    pA[2] = g_Whi + (size_t)(Hh+h0+arow)*Hh   + ach*8;
    pA[3] = g_Wlo + (size_t)(Hh+h0+arow)*Hh   + ach*8;
    const uint32_t aDst = (uint32_t)(arow*AROW + ach*16);
    // B: row = tid>>4 (0..15 = k within step), chunk = tid&15 (16B of 256B row)
    const int brow = tid >> 4, bch = tid & 15;
    const __nv_bfloat16* pBh = g_Yhi + ((size_t)b*Hh + brow)*Ll + l0 + bch*8;
    const __nv_bfloat16* pBl = g_Ylo + ((size_t)b*Hh + brow)*Ll + l0 + bch*8;
    const uint32_t bDst = (uint32_t)(brow*BROW + bch*16);

    // ldmatrix lane addressing
    const uint32_t a_off = (uint32_t)((lane & 15)*AROW + (lane >> 4)*16);
    // B trans: lanes 0-7: k0-7 @n0; 8-15: k8-15 @n0; 16-23: k0-7 @n8; 24-31: k8-15 @n8
    const uint32_t b_off = (uint32_t)(((lane & 7) + ((lane >> 3) & 1)*8)*BROW
                                      + (lane >> 4)*16);

    float acc_a[4][4][4], acc_g[4][4][4];
    #pragma unroll
    for (int i = 0; i < 4; ++i)
        #pragma unroll
        for (int j = 0; j < 4; ++j)
            #pragma unroll
            for (int q = 0; q < 4; ++q) { acc_a[i][j][q] = 0.f; acc_g[i][j][q] = 0.f; }

    // ---- pipeline prologue: stages 0,1 ----
    #pragma unroll
    for (int s = 0; s < 2; ++s) {
        uint32_t st = sb + (uint32_t)s*STAGEB;
        #pragma unroll
        for (int t = 0; t < 4; ++t)
            cpa16(st + t*ABUF + aDst, pA[t] + s*16);
        cpa16(st + BOFF + bDst,        pBh + (size_t)s*16*Ll);
        cpa16(st + BOFF + BBUF + bDst, pBl + (size_t)s*16*Ll);
        asm volatile("cp.async.commit_group;" ::: "memory");
    }

    int cur_s = 0;
    #pragma unroll 1
    for (int ks = 0; ks < 16; ++ks) {
        if (ks < 15) asm volatile("cp.async.wait_group 1;" ::: "memory");
        else         asm volatile("cp.async.wait_group 0;" ::: "memory");
        __syncthreads();
        if (ks + 2 < 16) {
            int s = ks + 2;
            int ss = cur_s + 2; if (ss >= 3) ss -= 3;
            uint32_t st = sb + (uint32_t)ss*STAGEB;
            #pragma unroll
            for (int t = 0; t < 4; ++t)
                cpa16(st + t*ABUF + aDst, pA[t] + s*16);
            cpa16(st + BOFF + bDst,        pBh + (size_t)s*16*Ll);
            cpa16(st + BOFF + BBUF + bDst, pBl + (size_t)s*16*Ll);
            asm volatile("cp.async.commit_group;" ::: "memory");
        }
        const uint32_t cur = sb + (uint32_t)cur_s*STAGEB;

        // ---- B fragments via ldmatrix.trans ----
        uint32_t bh[8], bl[8];
        {
            uint32_t bas_h = cur + BOFF + b_off + (uint32_t)(wn*64);
            uint32_t bas_l = bas_h + BBUF;
            ldsm4t(&bh[0], bas_h);        // n blocks 0,1
            ldsm4t(&bh[4], bas_h + 32);   // n blocks 2,3
            ldsm4t(&bl[0], bas_l);
            ldsm4t(&bl[4], bas_l + 32);
        }
        #pragma unroll
        for (int i = 0; i < 4; ++i) {
            uint32_t moff = (uint32_t)(wm*64 + i*16)*AROW + a_off;
            uint32_t ah[4], al[4];
            ldsm4(ah, cur + 0*ABUF + moff);
            ldsm4(al, cur + 1*ABUF + moff);
            #pragma unroll
            for (int j = 0; j < 4; ++j) {
                mma16816(acc_a[i][j], ah, bh[2*j], bh[2*j+1]);
                mma16816(acc_a[i][j], ah, bl[2*j], bl[2*j+1]);
                mma16816(acc_a[i][j], al, bh[2*j], bh[2*j+1]);
            }
            ldsm4(ah, cur + 2*ABUF + moff);
            ldsm4(al, cur + 3*ABUF + moff);
            #pragma unroll
            for (int j = 0; j < 4; ++j) {
                mma16816(acc_g[i][j], ah, bh[2*j], bh[2*j+1]);
                mma16816(acc_g[i][j], ah, bl[2*j], bl[2*j+1]);
                mma16816(acc_g[i][j], al, bh[2*j], bh[2*j+1]);
            }
        }
        if (++cur_s == 3) cur_s = 0;
    }

    // ---- epilogue: bias + GLU, in-register ----
    #pragma unroll
    for (int i = 0; i < 4; ++i) {
        int hr = h0 + wm*64 + i*16 + (lane >> 2);
        float ba0 = bias[hr],     bg0 = bias[Hh + hr];
        float ba1 = bias[hr + 8], bg1 = bias[Hh + hr + 8];
        #pragma unroll
        for (int j = 0; j < 4; ++j) {
            int col = l0 + wn*32 + j*8 + (lane & 3)*2;
            float a0 = acc_a[i][j][0] + ba0, g0 = acc_g[i][j][0] + bg0;
            float a1 = acc_a[i][j][1] + ba0, g1 = acc_g[i][j][1] + bg0;
            float a2 = acc_a[i][j][2] + ba1, g2 = acc_g[i][j][2] + bg1;
            float a3 = acc_a[i][j][3] + ba1, g3 = acc_g[i][j][3] + bg1;
            float2 v0 = make_float2(a0 / (1.0f + expf(-g0)),
                                    a1 / (1.0f + expf(-g1)));
            float2 v1 = make_float2(a2 / (1.0f + expf(-g2)),
                                    a3 / (1.0f + expf(-g3)));
            *(float2*)(out + ((size_t)b*Hh + hr)*Ll + col)     = v0;
            *(float2*)(out + ((size_t)b*Hh + hr + 8)*Ll + col) = v1;
        }
    }
}

// ============================================================
extern "C" void kernel_launch(void* const* d_in, const int* in_sizes, int n_in,
                              void* d_out, int out_size) {
    const float* u       = (const float*)d_in[0];
    const float* log_dt  = (const float*)d_in[1];
    const float* C       = (const float*)d_in[2];
    const float* lar     = (const float*)d_in[3];
    const float* aim     = (const float*)d_in[4];
    const float* D       = (const float*)d_in[5];
    const float* Wm      = (const float*)d_in[6];
    const float* bias    = (const float*)d_in[7];
    float* out = (float*)d_out;

    cudaFuncSetAttribute(gemm_mma_kernel,
                         cudaFuncAttributeMaxDynamicSharedMemorySize, GEMM_SMEM);

    prep_kernel<<<(Hh*N2d + 255)/256, 256>>>(log_dt, C, lar, aim);
    wsplit_kernel<<<(2*Hh*Hh + 255)/256, 256>>>(Wm);
    scan_kernel<<<(Bb*Hh)/8, 256>>>(u, D);
    dim3 grid(Ll/128, Hh/128, Bb);
    gemm_mma_kernel<<<grid, 256, GEMM_SMEM>>>(bias, out);
}